// round 10
// baseline (speedup 1.0000x reference)
#include <cuda_runtime.h>
#include <cuda_bf16.h>
#include <cstdint>
#include <cstddef>

#define T_STEPS 100
#define BATCH   256
#define HID     1024
#define N_IN    4096

#define NCTA    128
#define THREADS 512
#define GROUPS  8          // batch groups (32 rows each)
#define GSZ     16         // CTAs per group (N tiles)
#define MT      32         // batch rows per group
#define NT      64         // hidden cols per CTA
#define KC      256        // K chunk per warpgroup
#define SW      1032       // A smem row stride in bf16 (conflict-free ldmatrix)
#define XW      68         // xs row stride in floats
#define RSTR    72         // partial row stride in floats (conflict-free, 16B-aligned)
#define RED1    (MT * RSTR)            // floats per wg partial tile
#define REDSZ   (4 * RED1)             // floats per buffer (4 wgs)

// ---------------- device scratch ----------------
__device__ __nv_bfloat16 g_hidden[(size_t)(T_STEPS + 1) * BATCH * HID];
__device__ float         g_WxT[(size_t)N_IN * HID];             // Wx^T with (bm+bx) folded
__device__ int           g_ready[(T_STEPS + 1) * GROUPS * 4];   // per-chunk arrive counters
__device__ unsigned      g_count;                               // full-grid barrier
__device__ unsigned      g_gen;

// ---------------- helpers ----------------
__device__ __forceinline__ uint32_t smem_u32(const void* p) {
    return (uint32_t)__cvta_generic_to_shared(p);
}
__device__ __forceinline__ void ldmx4(uint32_t& r0, uint32_t& r1, uint32_t& r2, uint32_t& r3,
                                      uint32_t addr) {
    asm volatile("ldmatrix.sync.aligned.m8n8.x4.shared.b16 {%0,%1,%2,%3},[%4];\n"
                 : "=r"(r0), "=r"(r1), "=r"(r2), "=r"(r3) : "r"(addr));
}
__device__ __forceinline__ void mma16816(float* c, uint32_t a0, uint32_t a1, uint32_t a2,
                                         uint32_t a3, uint32_t b0, uint32_t b1) {
    asm volatile("mma.sync.aligned.m16n8k16.row.col.f32.bf16.bf16.f32 "
                 "{%0,%1,%2,%3},{%4,%5,%6,%7},{%8,%9},{%0,%1,%2,%3};\n"
                 : "+f"(c[0]), "+f"(c[1]), "+f"(c[2]), "+f"(c[3])
                 : "r"(a0), "r"(a1), "r"(a2), "r"(a3), "r"(b0), "r"(b1));
}
__device__ __forceinline__ void cp16(uint32_t dst, const void* src) {
    asm volatile("cp.async.cg.shared.global [%0],[%1],16;\n" :: "r"(dst), "l"(src));
}
__device__ __forceinline__ int ld_acq(const int* p) {
    int v;
    asm volatile("ld.acquire.gpu.global.b32 %0,[%1];" : "=r"(v) : "l"(p) : "memory");
    return v;
}
__device__ __forceinline__ void bar_sync(int id, int cnt) {
    asm volatile("bar.sync %0, %1;" :: "r"(id), "r"(cnt) : "memory");
}
__device__ __forceinline__ void bar_arrive(int id, int cnt) {
    asm volatile("bar.arrive %0, %1;" :: "r"(id), "r"(cnt) : "memory");
}

__device__ __forceinline__ void grid_barrier(int tid) {
    __syncthreads();
    if (tid == 0) {
        __threadfence();
        unsigned gen = atomicAdd(&g_gen, 0u);
        unsigned old = atomicAdd(&g_count, 1u);
        if (old == NCTA - 1) {
            atomicExch(&g_count, 0u);
            __threadfence();
            atomicAdd(&g_gen, 1u);
        } else {
            while (*(volatile unsigned*)&g_gen == gen) { }
        }
        __threadfence();
    }
    __syncthreads();
}

// ---------------- single fused persistent kernel ----------------
__global__ void __launch_bounds__(THREADS, 1) rnn_kernel(
    const int* __restrict__ x_idx, const int* __restrict__ y_idx,
    const float* __restrict__ truth, const float* __restrict__ Wm,
    const float* __restrict__ bm, const float* __restrict__ Wx,
    const float* __restrict__ bx, const float* __restrict__ Wy,
    const float* __restrict__ by, const float* __restrict__ b_start,
    float* __restrict__ out) {
    extern __shared__ __align__(16) char smem_raw[];
    __nv_bfloat16* a_s = (__nv_bfloat16*)smem_raw;        // 32 x SW bf16 (full h tile)
    float*         xs  = (float*)(a_s + MT * SW);         // 32 x XW floats (+xpose stage)
    float*         red = xs + MT * XW;                    // 2 x REDSZ floats (dbuf partials)

    const int tid  = threadIdx.x;
    const int warp = tid >> 5, lane = tid & 31;
    const int wg   = warp >> 2;        // K chunk this warpgroup owns (0..3)
    const int nw   = warp & 3;         // N16 subtile within CTA (0..3)
    const int wtid = tid & 127;
    const int grp = blockIdx.x >> 4;   // batch group (8)
    const int nt  = blockIdx.x & 15;   // N tile within group (16)
    const int m0 = grp * MT;
    const int n0 = nt * NT;

    // ---- prologue: h0 = b_start broadcast ----
    for (int i = tid; i < MT * (NT / 2); i += THREADS) {
        int r = i >> 5, c2 = i & 31;
        __nv_bfloat162 v = __floats2bfloat162_rn(b_start[n0 + c2 * 2],
                                                 b_start[n0 + c2 * 2 + 1]);
        *(__nv_bfloat162*)&g_hidden[(size_t)(m0 + r) * HID + n0 + c2 * 2] = v;
    }

    // ---- prologue: transpose Wx slice with (bm+bx) folded ----
    {
        float (*tile)[33] = (float (*)[33])xs;
        int x0 = blockIdx.x * 32;
        int tx = lane, ty = warp;        // 32 x 16
        for (int yt = 0; yt < HID / 32; yt++) {
            int y0 = yt * 32;
            for (int i = ty; i < 32; i += 16)
                tile[i][tx] = Wx[(size_t)(y0 + i) * N_IN + x0 + tx];
            __syncthreads();
            for (int i = ty; i < 32; i += 16)
                g_WxT[(size_t)(x0 + i) * HID + y0 + tx] = tile[tx][i] + bm[y0 + tx] + bx[y0 + tx];
            __syncthreads();
        }
    }

    // ---- prologue: preload B fragments (Wm) into registers, ONCE ----
    uint32_t breg[16][4];
    {
        const int nb = n0 + nw * 16 + (lane >> 2);
        const int kb = wg * KC + (lane & 3) * 2;
        #pragma unroll
        for (int kk = 0; kk < 16; kk++) {
            #pragma unroll
            for (int j = 0; j < 4; j++) {
                const float2 v = *(const float2*)&Wm[(size_t)(nb + (j >> 1) * 8) * HID
                                                     + kb + kk * 16 + (j & 1) * 8];
                ((__nv_bfloat162*)&breg[kk][j])[0] = __floats2bfloat162_rn(v.x, v.y);
            }
        }
    }
    __threadfence();
    grid_barrier(tid);   // WxT + h0 visible everywhere

    // A ldmatrix lane base (row = lane&15, k-half = lane>>4)
    const uint32_t a_lane = smem_u32(a_s) +
        (uint32_t)(((lane & 15) * SW + ((lane >> 4) << 3)) * 2);
    const int cp_row = wtid >> 2, cp_q4 = wtid & 3;
    const uint32_t cp_dst_row = smem_u32(a_s) + (uint32_t)(cp_row * SW * 2);
    const int mych = nt >> 2;            // the K-chunk this CTA's output belongs to
    // output-parallel epilogue assignment (thread-private across steps)
    const int erow = tid >> 4;           // 0..31 (wg-private 8-row band)
    const int ecol = (tid & 15) * 4;     // 0..60

    // ---- mainloop ----
    for (int t = 0; t < T_STEPS; t++) {
        // thread-private x gather: writes EXACTLY the xs float4 this thread reads later
        {
            int x = x_idx[t * BATCH + m0 + erow];
            *(float4*)&xs[erow * XW + ecol] =
                *(const float4*)&g_WxT[(size_t)x * HID + n0 + ecol];
        }

        // gate + load THIS warpgroup's K-chunk (M32 x 256 cols = 16KB)
        if (t > 0) {
            if (wtid == 0) {
                const int* f = &g_ready[(t * GROUPS + grp) * 4 + wg];
                while (ld_acq(f) < 4) { }
            }
            bar_sync(1 + wg, 128);
        }
        {
            const __nv_bfloat16* rowp = g_hidden + (size_t)t * BATCH * HID
                                      + (size_t)(m0 + cp_row) * HID;
            #pragma unroll
            for (int q = 0; q < 8; q++) {
                int c8 = wg * 32 + cp_q4 * 8 + q;
                cp16(cp_dst_row + (uint32_t)(c8 * 16), rowp + c8 * 8);
            }
            asm volatile("cp.async.commit_group;" ::: "memory");
            asm volatile("cp.async.wait_group 0;" ::: "memory");
            bar_sync(1 + wg, 128);
        }

        // MMA: A from smem (2 ldmx4/iter), B from registers
        float acc[2][2][4];
        #pragma unroll
        for (int i = 0; i < 2; i++)
            #pragma unroll
            for (int j = 0; j < 2; j++)
                acc[i][j][0] = acc[i][j][1] = acc[i][j][2] = acc[i][j][3] = 0.f;
        #pragma unroll
        for (int kk = 0; kk < 16; kk++) {
            const uint32_t kbyte = (uint32_t)((wg * KC + kk * 16) * 2);
            uint32_t a0, a1, a2, a3, a4, a5, a6, a7;
            ldmx4(a0, a1, a2, a3, a_lane + kbyte);                            // rows 0-15
            ldmx4(a4, a5, a6, a7, a_lane + (uint32_t)(16 * SW * 2) + kbyte);  // rows 16-31
            mma16816(acc[0][0], a0, a1, a2, a3, breg[kk][0], breg[kk][1]);
            mma16816(acc[0][1], a0, a1, a2, a3, breg[kk][2], breg[kk][3]);
            mma16816(acc[1][0], a4, a5, a6, a7, breg[kk][0], breg[kk][1]);
            mma16816(acc[1][1], a4, a5, a6, a7, breg[kk][2], breg[kk][3]);
        }

        // all wgs store partials (double-buffered, conflict-aware layout)
        float* Pw = red + (t & 1) * REDSZ + wg * RED1;
        {
            const int rb = lane >> 2, cb = (lane & 3) * 2;
            #pragma unroll
            for (int mi = 0; mi < 2; mi++)
                #pragma unroll
                for (int ni = 0; ni < 2; ni++)
                    #pragma unroll
                    for (int half = 0; half < 2; half++) {
                        int row = mi * 16 + rb + half * 8;
                        int col = nw * 16 + ni * 8 + cb;
                        *(float2*)&Pw[row * RSTR + col] =
                            make_float2(acc[mi][ni][half * 2], acc[mi][ni][half * 2 + 1]);
                    }
        }
        bar_sync(5, THREADS);

        // output-parallel reduce + epilogue: 4 elements per thread
        {
            const float* Pb = red + (t & 1) * REDSZ;
            float4 s = *(const float4*)&Pb[0 * RED1 + erow * RSTR + ecol];
            #pragma unroll
            for (int p = 1; p < 4; p++) {
                float4 v = *(const float4*)&Pb[p * RED1 + erow * RSTR + ecol];
                s.x += v.x; s.y += v.y; s.z += v.z; s.w += v.w;
            }
            float4 xv = *(const float4*)&xs[erow * XW + ecol];
            float v0 = s.x + xv.x, v1 = s.y + xv.y, v2 = s.z + xv.z, v3 = s.w + xv.w;
            asm("tanh.approx.f32 %0, %0;" : "+f"(v0));
            asm("tanh.approx.f32 %0, %0;" : "+f"(v1));
            asm("tanh.approx.f32 %0, %0;" : "+f"(v2));
            asm("tanh.approx.f32 %0, %0;" : "+f"(v3));
            uint2 pk;
            ((__nv_bfloat162*)&pk)[0] = __floats2bfloat162_rn(v0, v1);
            ((__nv_bfloat162*)&pk)[1] = __floats2bfloat162_rn(v2, v3);
            *(uint2*)&g_hidden[(size_t)(t + 1) * BATCH * HID
                               + (size_t)(m0 + erow) * HID + n0 + ecol] = pk;
        }

        // publish: fenced stores -> bar 6 -> wg0 flags; wgs 1-3 run ahead
        __threadfence();
        if (wg == 0) {
            bar_sync(6, THREADS);
            if (wtid == 0)
                atomicAdd(&g_ready[((t + 1) * GROUPS + grp) * 4 + mych], 1);
        } else {
            bar_arrive(6, THREADS);
        }
    }

    // ---- fused logits / pred / loss ----
    if (tid == 0) {
        const int* f = &g_ready[(T_STEPS * GROUPS + grp) * 4];
        #pragma unroll
        for (int c = 0; c < 4; c++)
            while (ld_acq(f + c) < 4) { }
    }
    __syncthreads();

    for (int i = 0; i < 13; i++) {
        int j = i * 16 + warp;               // 200 samples per CTA
        if (j >= 200) break;
        int jj = nt * 200 + j;
        int t  = jj >> 5;
        int bl = jj & 31;
        int gw = t * BATCH + m0 + bl;
        int y  = y_idx[gw];
        const __nv_bfloat16* h = g_hidden + (size_t)(t + 1) * BATCH * HID
                               + (size_t)(m0 + bl) * HID;
        const float* wy = Wy + (size_t)y * HID;
        float acc = 0.f;
        #pragma unroll
        for (int p = 0; p < 4; p++) {
            int k = p * 256 + lane * 8;
            uint4 hv = *(const uint4*)(h + k);
            const float4* w4 = (const float4*)(wy + k);
            float4 w0 = w4[0], w1 = w4[1];
            const __nv_bfloat162* hb = (const __nv_bfloat162*)&hv;
            float2 f0 = __bfloat1622float2(hb[0]);
            float2 f1 = __bfloat1622float2(hb[1]);
            float2 f2 = __bfloat1622float2(hb[2]);
            float2 f3 = __bfloat1622float2(hb[3]);
            acc += f0.x * w0.x + f0.y * w0.y + f1.x * w0.z + f1.y * w0.w
                 + f2.x * w1.x + f2.y * w1.y + f3.x * w1.z + f3.y * w1.w;
        }
        #pragma unroll
        for (int o = 16; o; o >>= 1) acc += __shfl_xor_sync(0xffffffffu, acc, o);
        if (lane == 0) {
            float logit = acc + by[y];
            float pred = 1.f / (1.f + expf(-logit));
            float tr = truth[gw];
            float lsp = fminf(logit, 0.f)  - log1pf(expf(-fabsf(logit)));
            float lsn = fminf(-logit, 0.f) - log1pf(expf(-fabsf(logit)));
            out[gw] = pred;
            out[T_STEPS * BATCH + gw] = -(tr * lsp + (1.f - tr) * lsn);
        }
    }

    // ---- reset arrive counters for the next graph replay ----
    grid_barrier(tid);     // nobody still polling
    for (int i = blockIdx.x * THREADS + tid; i < (T_STEPS + 1) * GROUPS * 4;
         i += NCTA * THREADS)
        g_ready[i] = 0;
    __threadfence();
    grid_barrier(tid);     // resets visible before exit
}

// ---------------- launch ----------------
extern "C" void kernel_launch(void* const* d_in, const int* in_sizes, int n_in,
                              void* d_out, int out_size) {
    (void)in_sizes; (void)n_in; (void)out_size;
    const int*   x_idx   = (const int*)d_in[0];
    const int*   y_idx   = (const int*)d_in[1];
    const float* truth   = (const float*)d_in[2];
    const float* Wm      = (const float*)d_in[3];
    const float* bm      = (const float*)d_in[4];
    const float* Wx      = (const float*)d_in[5];
    const float* bx      = (const float*)d_in[6];
    const float* Wy      = (const float*)d_in[7];
    const float* by      = (const float*)d_in[8];
    // d_in[9] = W_start: multiplied by zeros -> unused
    const float* b_start = (const float*)d_in[10];
    float* out = (float*)d_out;

    // smem: A tile + xs + double-buffered partials = ~145 KB
    const int smem_bytes = MT * SW * 2 + (MT * XW + 2 * REDSZ) * 4;
    cudaFuncSetAttribute(rnn_kernel, cudaFuncAttributeMaxDynamicSharedMemorySize, smem_bytes);
    rnn_kernel<<<NCTA, THREADS, smem_bytes>>>(x_idx, y_idx, truth, Wm, bm, Wx, bx,
                                              Wy, by, b_start, out);
}

// round 11
// speedup vs baseline: 1.1420x; 1.1420x over previous
#include <cuda_runtime.h>
#include <cuda_bf16.h>
#include <cstdint>
#include <cstddef>

#define T_STEPS 100
#define BATCH   256
#define HID     1024
#define N_IN    4096

#define NCTA    128
#define THREADS 512
#define GROUPS  8          // batch groups (32 rows each)
#define GSZ     16         // CTAs per group (N tiles)
#define MT      32         // batch rows per group
#define NT      64         // hidden cols per CTA
#define KC      256        // K chunk per warpgroup
#define SW      1032       // A smem row stride in bf16 (conflict-free ldmatrix)
#define XW      68         // xs row stride in floats
#define RSTRIDE 20         // red row stride in floats (16B-aligned, conflict-free)
#define REDSZ   (3 * 128 * RSTRIDE)   // floats per red buffer

// ---------------- device scratch ----------------
__device__ __nv_bfloat16 g_hidden[(size_t)(T_STEPS + 1) * BATCH * HID];
__device__ float         g_WxT[(size_t)N_IN * HID];             // Wx^T with (bm+bx) folded
__device__ int           g_ready[(T_STEPS + 1) * GROUPS * 4];   // per-chunk arrive counters
__device__ unsigned      g_count;                               // full-grid barrier
__device__ unsigned      g_gen;

// ---------------- helpers ----------------
__device__ __forceinline__ uint32_t smem_u32(const void* p) {
    return (uint32_t)__cvta_generic_to_shared(p);
}
__device__ __forceinline__ void ldmx4(uint32_t& r0, uint32_t& r1, uint32_t& r2, uint32_t& r3,
                                      uint32_t addr) {
    asm volatile("ldmatrix.sync.aligned.m8n8.x4.shared.b16 {%0,%1,%2,%3},[%4];\n"
                 : "=r"(r0), "=r"(r1), "=r"(r2), "=r"(r3) : "r"(addr));
}
__device__ __forceinline__ void mma16816(float* c, uint32_t a0, uint32_t a1, uint32_t a2,
                                         uint32_t a3, uint32_t b0, uint32_t b1) {
    asm volatile("mma.sync.aligned.m16n8k16.row.col.f32.bf16.bf16.f32 "
                 "{%0,%1,%2,%3},{%4,%5,%6,%7},{%8,%9},{%0,%1,%2,%3};\n"
                 : "+f"(c[0]), "+f"(c[1]), "+f"(c[2]), "+f"(c[3])
                 : "r"(a0), "r"(a1), "r"(a2), "r"(a3), "r"(b0), "r"(b1));
}
__device__ __forceinline__ void cp16(uint32_t dst, const void* src) {
    asm volatile("cp.async.cg.shared.global [%0],[%1],16;\n" :: "r"(dst), "l"(src));
}
__device__ __forceinline__ int ld_acq(const int* p) {
    int v;
    asm volatile("ld.acquire.gpu.global.b32 %0,[%1];" : "=r"(v) : "l"(p) : "memory");
    return v;
}
__device__ __forceinline__ void bar_sync(int id, int cnt) {
    asm volatile("bar.sync %0, %1;" :: "r"(id), "r"(cnt) : "memory");
}
__device__ __forceinline__ void bar_arrive(int id, int cnt) {
    asm volatile("bar.arrive %0, %1;" :: "r"(id), "r"(cnt) : "memory");
}

__device__ __forceinline__ void grid_barrier(int tid) {
    __syncthreads();
    if (tid == 0) {
        __threadfence();
        unsigned gen = atomicAdd(&g_gen, 0u);
        unsigned old = atomicAdd(&g_count, 1u);
        if (old == NCTA - 1) {
            atomicExch(&g_count, 0u);
            __threadfence();
            atomicAdd(&g_gen, 1u);
        } else {
            while (*(volatile unsigned*)&g_gen == gen) { }
        }
        __threadfence();
    }
    __syncthreads();
}

// ---------------- single fused persistent kernel ----------------
__global__ void __launch_bounds__(THREADS, 1) rnn_kernel(
    const int* __restrict__ x_idx, const int* __restrict__ y_idx,
    const float* __restrict__ truth, const float* __restrict__ Wm,
    const float* __restrict__ bm, const float* __restrict__ Wx,
    const float* __restrict__ bx, const float* __restrict__ Wy,
    const float* __restrict__ by, const float* __restrict__ b_start,
    float* __restrict__ out) {
    extern __shared__ __align__(16) char smem_raw[];
    __nv_bfloat16* a_s = (__nv_bfloat16*)smem_raw;        // 32 x SW bf16 (full h tile)
    float*         xs  = (float*)(a_s + MT * SW);         // 32 x XW floats (+xpose stage)
    float*         red = xs + MT * XW;                    // 2 x REDSZ floats (dbuf partials)

    const int tid  = threadIdx.x;
    const int warp = tid >> 5, lane = tid & 31;
    const int wg   = warp >> 2;        // K chunk this warpgroup owns (0..3)
    const int nw   = warp & 3;         // N16 subtile within CTA (0..3)
    const int wtid = tid & 127;
    const int grp = blockIdx.x >> 4;   // batch group (8)
    const int nt  = blockIdx.x & 15;   // N tile within group (16)
    const int m0 = grp * MT;
    const int n0 = nt * NT;

    // ---- prologue: h0 = b_start broadcast ----
    for (int i = tid; i < MT * (NT / 2); i += THREADS) {
        int r = i >> 5, c2 = i & 31;
        __nv_bfloat162 v = __floats2bfloat162_rn(b_start[n0 + c2 * 2],
                                                 b_start[n0 + c2 * 2 + 1]);
        *(__nv_bfloat162*)&g_hidden[(size_t)(m0 + r) * HID + n0 + c2 * 2] = v;
    }

    // ---- prologue: transpose Wx slice with (bm+bx) folded ----
    {
        float (*tile)[33] = (float (*)[33])xs;
        int x0 = blockIdx.x * 32;
        int tx = lane, ty = warp;        // 32 x 16
        for (int yt = 0; yt < HID / 32; yt++) {
            int y0 = yt * 32;
            for (int i = ty; i < 32; i += 16)
                tile[i][tx] = Wx[(size_t)(y0 + i) * N_IN + x0 + tx];
            __syncthreads();
            for (int i = ty; i < 32; i += 16)
                g_WxT[(size_t)(x0 + i) * HID + y0 + tx] = tile[tx][i] + bm[y0 + tx] + bx[y0 + tx];
            __syncthreads();
        }
    }

    // ---- prologue: preload B fragments (Wm) into registers, ONCE ----
    // warp covers N16 (cols n0+nw*16..+16) x K256 (cols wg*256..+256)
    uint32_t breg[16][4];
    {
        const int nb = n0 + nw * 16 + (lane >> 2);
        const int kb = wg * KC + (lane & 3) * 2;
        #pragma unroll
        for (int kk = 0; kk < 16; kk++) {
            #pragma unroll
            for (int j = 0; j < 4; j++) {
                const float2 v = *(const float2*)&Wm[(size_t)(nb + (j >> 1) * 8) * HID
                                                     + kb + kk * 16 + (j & 1) * 8];
                ((__nv_bfloat162*)&breg[kk][j])[0] = __floats2bfloat162_rn(v.x, v.y);
            }
        }
    }
    __threadfence();
    grid_barrier(tid);   // WxT + h0 visible everywhere

    // A ldmatrix lane base (row = lane&15, k-half = lane>>4)
    const uint32_t a_lane = smem_u32(a_s) +
        (uint32_t)(((lane & 15) * SW + ((lane >> 4) << 3)) * 2);
    const int cp_row = wtid >> 2, cp_q4 = wtid & 3;
    const uint32_t cp_dst_row = smem_u32(a_s) + (uint32_t)(cp_row * SW * 2);
    const int mych = nt >> 2;            // the K-chunk this CTA's output belongs to

    // ---- mainloop: per-chunk dataflow, wgs 1-3 run ahead of wg0's tail ----
    for (int t = 0; t < T_STEPS; t++) {
        // wg0 gathers x projection (it alone runs the epilogue)
        if (wg == 0) {
            const int r = wtid >> 2, seg = wtid & 3;
            int x = x_idx[t * BATCH + m0 + r];
            const float4* src = (const float4*)&g_WxT[(size_t)x * HID + n0 + seg * 16];
            float4* dst = (float4*)&xs[r * XW + seg * 16];
            dst[0] = src[0]; dst[1] = src[1]; dst[2] = src[2]; dst[3] = src[3];
        }

        // gate THIS warpgroup's K-chunk on its 4 producers
        if (t > 0) {
            if (wtid == 0) {
                const int* f = &g_ready[(t * GROUPS + grp) * 4 + wg];
                while (ld_acq(f) < 4) { }
            }
            bar_sync(1 + wg, 128);
        }

        // issue the chunk as TWO 128-col sub-chunks (double-buffered commit groups)
        {
            const __nv_bfloat16* rowp = g_hidden + (size_t)t * BATCH * HID
                                      + (size_t)(m0 + cp_row) * HID;
            #pragma unroll
            for (int q = 0; q < 4; q++) {
                int c8 = wg * 32 + cp_q4 * 4 + q;            // units 0..15 of chunk
                cp16(cp_dst_row + (uint32_t)(c8 * 16), rowp + c8 * 8);
            }
            asm volatile("cp.async.commit_group;" ::: "memory");
            #pragma unroll
            for (int q = 0; q < 4; q++) {
                int c8 = wg * 32 + 16 + cp_q4 * 4 + q;       // units 16..31 of chunk
                cp16(cp_dst_row + (uint32_t)(c8 * 16), rowp + c8 * 8);
            }
            asm volatile("cp.async.commit_group;" ::: "memory");
        }

        float acc[2][2][4];
        #pragma unroll
        for (int i = 0; i < 2; i++)
            #pragma unroll
            for (int j = 0; j < 2; j++)
                acc[i][j][0] = acc[i][j][1] = acc[i][j][2] = acc[i][j][3] = 0.f;

        // MMA sub0 while sub1 is still in flight
        asm volatile("cp.async.wait_group 1;" ::: "memory");
        bar_sync(1 + wg, 128);
        #pragma unroll
        for (int kk = 0; kk < 8; kk++) {
            const uint32_t kbyte = (uint32_t)((wg * KC + kk * 16) * 2);
            uint32_t a0, a1, a2, a3, a4, a5, a6, a7;
            ldmx4(a0, a1, a2, a3, a_lane + kbyte);
            ldmx4(a4, a5, a6, a7, a_lane + (uint32_t)(16 * SW * 2) + kbyte);
            mma16816(acc[0][0], a0, a1, a2, a3, breg[kk][0], breg[kk][1]);
            mma16816(acc[0][1], a0, a1, a2, a3, breg[kk][2], breg[kk][3]);
            mma16816(acc[1][0], a4, a5, a6, a7, breg[kk][0], breg[kk][1]);
            mma16816(acc[1][1], a4, a5, a6, a7, breg[kk][2], breg[kk][3]);
        }
        asm volatile("cp.async.wait_group 0;" ::: "memory");
        bar_sync(1 + wg, 128);
        #pragma unroll
        for (int kk = 8; kk < 16; kk++) {
            const uint32_t kbyte = (uint32_t)((wg * KC + kk * 16) * 2);
            uint32_t a0, a1, a2, a3, a4, a5, a6, a7;
            ldmx4(a0, a1, a2, a3, a_lane + kbyte);
            ldmx4(a4, a5, a6, a7, a_lane + (uint32_t)(16 * SW * 2) + kbyte);
            mma16816(acc[0][0], a0, a1, a2, a3, breg[kk][0], breg[kk][1]);
            mma16816(acc[0][1], a0, a1, a2, a3, breg[kk][2], breg[kk][3]);
            mma16816(acc[1][0], a4, a5, a6, a7, breg[kk][0], breg[kk][1]);
            mma16816(acc[1][1], a4, a5, a6, a7, breg[kk][2], breg[kk][3]);
        }

        float* af = &acc[0][0][0];
        float* rbuf = red + (t & 1) * REDSZ;
        if (wg != 0) {
            // publish partials (aligned float4, conflict-free stride 20) and run ahead
            float4* dst = (float4*)&rbuf[((wg - 1) * 128 + wtid) * RSTRIDE];
            #pragma unroll
            for (int q = 0; q < 4; q++) dst[q] = ((const float4*)af)[q];
            bar_arrive(5, THREADS);
        } else {
            bar_sync(5, THREADS);   // wait for wgs 1-3 partials
            #pragma unroll
            for (int p = 0; p < 3; p++) {
                const float4* src = (const float4*)&rbuf[(p * 128 + wtid) * RSTRIDE];
                #pragma unroll
                for (int q = 0; q < 4; q++) {
                    float4 v = src[q];
                    af[q * 4 + 0] += v.x; af[q * 4 + 1] += v.y;
                    af[q * 4 + 2] += v.z; af[q * 4 + 3] += v.w;
                }
            }

            // epilogue: + xproj(+bias), tanh.approx, pack bf16, store h[t+1]
            __nv_bfloat16* hout = g_hidden + (size_t)(t + 1) * BATCH * HID;
            const int r_base = lane >> 2;
            const int c_base = (lane & 3) * 2;
            #pragma unroll
            for (int mi = 0; mi < 2; mi++) {
                #pragma unroll
                for (int ni = 0; ni < 2; ni++) {
                    int col = nw * 16 + ni * 8 + c_base;
                    #pragma unroll
                    for (int half = 0; half < 2; half++) {
                        int row = mi * 16 + r_base + half * 8;
                        float v0 = acc[mi][ni][half * 2 + 0] + xs[row * XW + col];
                        float v1 = acc[mi][ni][half * 2 + 1] + xs[row * XW + col + 1];
                        asm("tanh.approx.f32 %0, %0;" : "+f"(v0));
                        asm("tanh.approx.f32 %0, %0;" : "+f"(v1));
                        *(__nv_bfloat162*)&hout[(size_t)(m0 + row) * HID + n0 + col] =
                            __floats2bfloat162_rn(v0, v1);
                    }
                }
            }
            bar_sync(6, 128);       // wg0 stores complete (also orders next xs gather)
            if (wtid == 0) {
                __threadfence();
                atomicAdd(&g_ready[((t + 1) * GROUPS + grp) * 4 + mych], 1);
            }
        }
    }

    // ---- fused logits / pred / loss ----
    if (tid == 0) {
        const int* f = &g_ready[(T_STEPS * GROUPS + grp) * 4];
        #pragma unroll
        for (int c = 0; c < 4; c++)
            while (ld_acq(f + c) < 4) { }
    }
    __syncthreads();

    for (int i = 0; i < 13; i++) {
        int j = i * 16 + warp;               // 200 samples per CTA
        if (j >= 200) break;
        int jj = nt * 200 + j;
        int t  = jj >> 5;
        int bl = jj & 31;
        int gw = t * BATCH + m0 + bl;
        int y  = y_idx[gw];
        const __nv_bfloat16* h = g_hidden + (size_t)(t + 1) * BATCH * HID
                               + (size_t)(m0 + bl) * HID;
        const float* wy = Wy + (size_t)y * HID;
        float acc = 0.f;
        #pragma unroll
        for (int p = 0; p < 4; p++) {
            int k = p * 256 + lane * 8;
            uint4 hv = *(const uint4*)(h + k);
            const float4* w4 = (const float4*)(wy + k);
            float4 w0 = w4[0], w1 = w4[1];
            const __nv_bfloat162* hb = (const __nv_bfloat162*)&hv;
            float2 f0 = __bfloat1622float2(hb[0]);
            float2 f1 = __bfloat1622float2(hb[1]);
            float2 f2 = __bfloat1622float2(hb[2]);
            float2 f3 = __bfloat1622float2(hb[3]);
            acc += f0.x * w0.x + f0.y * w0.y + f1.x * w0.z + f1.y * w0.w
                 + f2.x * w1.x + f2.y * w1.y + f3.x * w1.z + f3.y * w1.w;
        }
        #pragma unroll
        for (int o = 16; o; o >>= 1) acc += __shfl_xor_sync(0xffffffffu, acc, o);
        if (lane == 0) {
            float logit = acc + by[y];
            float pred = 1.f / (1.f + expf(-logit));
            float tr = truth[gw];
            float lsp = fminf(logit, 0.f)  - log1pf(expf(-fabsf(logit)));
            float lsn = fminf(-logit, 0.f) - log1pf(expf(-fabsf(logit)));
            out[gw] = pred;
            out[T_STEPS * BATCH + gw] = -(tr * lsp + (1.f - tr) * lsn);
        }
    }

    // ---- reset arrive counters for the next graph replay ----
    grid_barrier(tid);     // nobody still polling
    for (int i = blockIdx.x * THREADS + tid; i < (T_STEPS + 1) * GROUPS * 4;
         i += NCTA * THREADS)
        g_ready[i] = 0;
    __threadfence();
    grid_barrier(tid);     // resets visible before exit
}

// ---------------- launch ----------------
extern "C" void kernel_launch(void* const* d_in, const int* in_sizes, int n_in,
                              void* d_out, int out_size) {
    (void)in_sizes; (void)n_in; (void)out_size;
    const int*   x_idx   = (const int*)d_in[0];
    const int*   y_idx   = (const int*)d_in[1];
    const float* truth   = (const float*)d_in[2];
    const float* Wm      = (const float*)d_in[3];
    const float* bm      = (const float*)d_in[4];
    const float* Wx      = (const float*)d_in[5];
    const float* bx      = (const float*)d_in[6];
    const float* Wy      = (const float*)d_in[7];
    const float* by      = (const float*)d_in[8];
    // d_in[9] = W_start: multiplied by zeros -> unused
    const float* b_start = (const float*)d_in[10];
    float* out = (float*)d_out;

    // smem: A tile + xs + double-buffered reduction = ~135 KB
    const int smem_bytes = MT * SW * 2 + (MT * XW + 2 * REDSZ) * 4;
    cudaFuncSetAttribute(rnn_kernel, cudaFuncAttributeMaxDynamicSharedMemorySize, smem_bytes);
    rnn_kernel<<<NCTA, THREADS, smem_bytes>>>(x_idx, y_idx, truth, Wm, bm, Wx, bx,
                                              Wy, by, b_start, out);
}